// round 10
// baseline (speedup 1.0000x reference)
#include <cuda_runtime.h>
#include <cstdint>

#define EPS 1e-5f
#define NUM_GRAPHS 128
#define MAX_N 131072
#define F_CAP 100352            // quantized nodes held in smem (2B each)
#define NG_CAP 8192             // 16-node coarse batch groups
#define CTA_THREADS 768
#define WCHUNK4 256             // vec4-elements per warp ticket (8 iters)

#define QR    4.9f
#define QINV  (254.0f / (2.0f * QR))
// QSTEP^4 = 2.216e-6 ; EPS in product units = 4.51 ; CERT_MIN=64 keeps >10x margin
#define CERT_MIN 64

__device__ int            g_ticket;
__device__ unsigned char  g_batch8[MAX_N];
__device__ unsigned char  g_coarse16[NG_CAP];
__device__ unsigned short g_qpos16[F_CAP];

// Prologue: reset ticket, zero out, batch->u8, coarse table, quantize coords.
__global__ void prep_kernel(const int* __restrict__ batch_index,
                            const float2* __restrict__ pos,
                            float* __restrict__ out, int N, int F, int NG16) {
    int i = blockIdx.x * blockDim.x + threadIdx.x;
    if (i == 0) g_ticket = 0;
    if (i < NUM_GRAPHS) out[i] = 0.0f;
    if (i < N) g_batch8[i] = (unsigned char)batch_index[i];
    if (i < F) {
        float2 p = __ldg(pos + i);
        int qx = __float2int_rn((p.x + QR) * QINV);
        int qy = __float2int_rn((p.y + QR) * QINV);
        bool ok = (qx >= 0) & (qx <= 254) & (qy >= 0) & (qy <= 254)
                  & (p.x == p.x) & (p.y == p.y);
        g_qpos16[i] = ok ? (unsigned short)(qx | (qy << 8)) : (unsigned short)0xFFFF;
    }
    if (i < NG16) {
        int base = i << 4;
        int b0 = __ldg(batch_index + base);
        unsigned char v = (unsigned char)b0;
        int lim = min(16, N - base);
        for (int j = 1; j < lim; j++)
            if (__ldg(batch_index + base + j) != b0) { v = 255; break; }
        g_coarse16[i] = v;
    }
}

__device__ __forceinline__ bool xing_exact(float2 p1, float2 p2, float2 p3, float2 p4) {
    float rx = p4.x - p3.x, ry = p4.y - p3.y;
    float d1 = rx * (p1.y - p3.y) - ry * (p1.x - p3.x);
    float d2 = rx * (p2.y - p3.y) - ry * (p2.x - p3.x);
    float qx = p2.x - p1.x, qy = p2.y - p1.y;
    float d3 = qx * (p3.y - p1.y) - qy * (p3.x - p1.x);
    float d4 = qx * (p4.y - p1.y) - qy * (p4.x - p1.x);
    return (d1 * d2 < -EPS) & (d3 * d4 < -EPS);
}

__global__ void __launch_bounds__(CTA_THREADS, 1)
crossings_kernel(const float2* __restrict__ pos,
                 const int* __restrict__ epi,  // [2][2][P]: s1 | s2 | e1 | e2
                 float* __restrict__ out,
                 int P, int F, int NG16) {
    extern __shared__ char smem_raw[];
    unsigned short* s_q = (unsigned short*)smem_raw;                  // F_CAP*2
    unsigned char* s_coarse = (unsigned char*)(smem_raw + F_CAP * 2); // NG_CAP
    float* hist = (float*)(smem_raw + F_CAP * 2 + NG_CAP);

    // Preload quantized table + coarse batch table (coalesced int4 copies).
    {
        int n16 = (F * 2 + 15) >> 4;
        const uint4* src = (const uint4*)g_qpos16;
        uint4* dst = (uint4*)s_q;
        for (int i = threadIdx.x; i < n16; i += CTA_THREADS) dst[i] = src[i];
        int c16 = (NG16 + 15) >> 4;
        const uint4* csrc = (const uint4*)g_coarse16;
        uint4* cdst = (uint4*)s_coarse;
        for (int i = threadIdx.x; i < c16; i += CTA_THREADS) cdst[i] = csrc[i];
    }
    if (threadIdx.x < NUM_GRAPHS) hist[threadIdx.x] = 0.0f;
    __syncthreads();

    const int P4 = P >> 2;
    const int4* __restrict__ s1v = (const int4*)(epi);
    const int4* __restrict__ s2v = (const int4*)(epi + (size_t)P);
    const int4* __restrict__ e1v = (const int4*)(epi + 2 * (size_t)P);
    const int4* __restrict__ e2v = (const int4*)(epi + 3 * (size_t)P);

    const int lane = threadIdx.x & 31;

    // Warp-autonomous ticket loop over vec4 elements (4 pairs per element).
    while (true) {
        int base;
        if (lane == 0) base = atomicAdd(&g_ticket, WCHUNK4);
        base = __shfl_sync(0xFFFFFFFFu, base, 0);
        if (base >= P4) break;
        int lim = min(base + WCHUNK4, P4);

        for (int v = base + lane; v < lim; v += 32) {
            int4 s1 = __ldg(s1v + v);
            int4 s2 = __ldg(s2v + v);
            int4 e1 = __ldg(e1v + v);
            int4 e2 = __ldg(e2v + v);

            int ii[4][4] = {{s1.x, e1.x, s2.x, e2.x},
                            {s1.y, e1.y, s2.y, e2.y},
                            {s1.z, e1.z, s2.z, e2.z},
                            {s1.w, e1.w, s2.w, e2.w}};

            // Batch all 16 smem gathers first (MLP within the iteration).
            unsigned q[4][4];
            #pragma unroll
            for (int sl = 0; sl < 4; sl++)
                #pragma unroll
                for (int k = 0; k < 4; k++)
                    q[sl][k] = s_q[ii[sl][k]];

            #pragma unroll
            for (int sl = 0; sl < 4; sl++) {
                unsigned q1 = q[sl][0], q2 = q[sl][1], q3 = q[sl][2], q4 = q[sl][3];
                int i1 = ii[sl][0];
                bool sent = (max(max(q1, q2), max(q3, q4)) == 0xFFFFu);

                int X1 = q1 & 0xFF, Y1 = q1 >> 8;
                int X2 = q2 & 0xFF, Y2 = q2 >> 8;
                int X3 = q3 & 0xFF, Y3 = q3 >> 8;
                int X4 = q4 & 0xFF, Y4 = q4 >> 8;

                // Exact integer orientation values on the quantized grid.
                int Rx = X4 - X3, Ry = Y4 - Y3;
                int Ax = X1 - X3, Ay = Y1 - Y3;
                int Bx = X2 - X3, By = Y2 - Y3;
                int d1 = Rx * Ay - Ry * Ax;
                int d2 = Rx * By - Ry * Bx;
                int Ux = X2 - X1, Uy = Y2 - Y1;
                int Cx = X3 - X1, Cy = Y3 - Y1;
                int Ex = X4 - X1, Ey = Y4 - Y1;
                int d3 = Ux * Cy - Uy * Cx;
                int d4 = Ux * Ey - Uy * Ex;

                // Error bounds in grid units: |d_true - d_int| <= S + 2.
                int sR = abs(Rx) + abs(Ry);
                int sU = abs(Ux) + abs(Uy);
                int l1 = abs(d1) - (sR + abs(Ax) + abs(Ay) + 2);
                int l2 = abs(d2) - (sR + abs(Bx) + abs(By) + 2);
                int l3 = abs(d3) - (sU + abs(Cx) + abs(Cy) + 2);
                int l4 = abs(d4) - (sU + abs(Ex) + abs(Ey) + 2);

                bool okA = (l1 > 0) & (l2 > 0) &
                           (min(l1, 32767) * min(l2, 32767) > CERT_MIN);
                bool okB = (l3 > 0) & (l4 > 0) &
                           (min(l3, 32767) * min(l4, 32767) > CERT_MIN);
                bool oppA = ((d1 ^ d2) < 0);
                bool oppB = ((d3 ^ d4) < 0);
                bool ctA = okA & oppA, cfA = okA & !oppA;
                bool ctB = okB & oppB, cfB = okB & !oppB;

                bool cross = ctA & ctB;
                if (sent | (!(ctA & ctB) & !(cfA | cfB))) {
                    // Uncertain: exact fp32 re-test via L1tex (rare lanes).
                    cross = xing_exact(__ldg(pos + ii[sl][0]), __ldg(pos + ii[sl][1]),
                                       __ldg(pos + ii[sl][2]), __ldg(pos + ii[sl][3]));
                }
                if (cross) {
                    unsigned char b = s_coarse[i1 >> 4];
                    if (b == 255) b = g_batch8[i1];
                    atomicAdd(&hist[b], 1.0f);
                }
            }
        }
    }

    // Scalar tail (P not divisible by 4) — exact path, block 0 only.
    if (blockIdx.x == 0) {
        for (int p = (P4 << 2) + threadIdx.x; p < P; p += blockDim.x) {
            int t1 = __ldg(epi + p);
            int t2 = __ldg(epi + (size_t)P + p);
            int t3 = __ldg(epi + 2 * (size_t)P + p);
            int t4 = __ldg(epi + 3 * (size_t)P + p);
            if (xing_exact(__ldg(pos + t1), __ldg(pos + t3),
                           __ldg(pos + t2), __ldg(pos + t4)))
                atomicAdd(&hist[g_batch8[t1]], 1.0f);
        }
    }

    __syncthreads();
    for (int i = threadIdx.x; i < NUM_GRAPHS; i += CTA_THREADS) {
        float h = hist[i];
        if (h != 0.0f) atomicAdd(&out[i], h);
    }
}

extern "C" void kernel_launch(void* const* d_in, const int* in_sizes, int n_in,
                              void* d_out, int out_size) {
    // metadata order: node_pos f32[N,2], edge_index i32[2,E] (UNUSED),
    //                 apsp f32[E] (UNUSED), batch_index i32[N],
    //                 edge_pair_index i32[2,2,P]
    const float2* pos = (const float2*)d_in[0];
    const int* batch_index = (const int*)d_in[3];
    const int* epi = (const int*)d_in[4];
    float* out = (float*)d_out;

    int N = in_sizes[0] / 2;
    if (N > F_CAP) N = F_CAP;          // scratch bound (N is 100000 by spec)
    int P = in_sizes[4] / 4;
    int F = N;
    int NG16 = (N + 15) >> 4;
    if (NG16 > NG_CAP) NG16 = NG_CAP;

    int prep_threads = 256;
    int prep_blocks = (N + prep_threads - 1) / prep_threads;
    prep_kernel<<<prep_blocks, prep_threads>>>(batch_index, pos, out, N, F, NG16);

    size_t smem_bytes = (size_t)F_CAP * 2 + NG_CAP + NUM_GRAPHS * sizeof(float);
    cudaFuncSetAttribute(crossings_kernel,
                         cudaFuncAttributeMaxDynamicSharedMemorySize,
                         (int)smem_bytes);

    crossings_kernel<<<148, CTA_THREADS, smem_bytes>>>(pos, epi, out, P, F, NG16);
}

// round 12
// speedup vs baseline: 1.0295x; 1.0295x over previous
#include <cuda_runtime.h>
#include <cstdint>

#define EPS 1e-5f
#define NUM_GRAPHS 128
#define MAX_N 131072
#define F_CAP 100352            // quantized nodes held in smem (2B each)
#define NG_CAP 8192             // 16-node coarse batch groups
#define CTA_THREADS 768
#define WCHUNK 512              // vec2-elements per warp ticket (16 iters)

#define QR    4.9f
#define QINV  (254.0f / (2.0f * QR))
// QSTEP^4 = 2.216e-6 ; EPS in product units = 4.51 ; CERT_MIN=64 keeps >10x margin
#define CERT_MIN 64
#define ONES4 0x01010101u

__device__ int            g_ticket;
__device__ unsigned char  g_batch8[MAX_N];
__device__ unsigned char  g_coarse16[NG_CAP];
__device__ unsigned short g_qpos16[F_CAP];

// Prologue: reset ticket, zero out, batch->u8, coarse table, quantize coords.
__global__ void prep_kernel(const int* __restrict__ batch_index,
                            const float2* __restrict__ pos,
                            float* __restrict__ out, int N, int F, int NG16) {
    int i = blockIdx.x * blockDim.x + threadIdx.x;
    if (i == 0) g_ticket = 0;
    if (i < NUM_GRAPHS) out[i] = 0.0f;
    if (i < N) g_batch8[i] = (unsigned char)batch_index[i];
    if (i < F) {
        float2 p = __ldg(pos + i);
        int qx = __float2int_rn((p.x + QR) * QINV);
        int qy = __float2int_rn((p.y + QR) * QINV);
        bool ok = (qx >= 0) & (qx <= 254) & (qy >= 0) & (qy <= 254)
                  & (p.x == p.x) & (p.y == p.y);
        g_qpos16[i] = ok ? (unsigned short)(qx | (qy << 8)) : (unsigned short)0xFFFF;
    }
    if (i < NG16) {
        int base = i << 4;
        int b0 = __ldg(batch_index + base);
        unsigned char v = (unsigned char)b0;
        int lim = min(16, N - base);
        for (int j = 1; j < lim; j++)
            if (__ldg(batch_index + base + j) != b0) { v = 255; break; }
        g_coarse16[i] = v;
    }
}

__device__ __forceinline__ bool xing_exact(float2 p1, float2 p2, float2 p3, float2 p4) {
    float rx = p4.x - p3.x, ry = p4.y - p3.y;
    float d1 = rx * (p1.y - p3.y) - ry * (p1.x - p3.x);
    float d2 = rx * (p2.y - p3.y) - ry * (p2.x - p3.x);
    float qx = p2.x - p1.x, qy = p2.y - p1.y;
    float d3 = qx * (p3.y - p1.y) - qy * (p3.x - p1.x);
    float d4 = qx * (p4.y - p1.y) - qy * (p4.x - p1.x);
    return (d1 * d2 < -EPS) & (d3 * d4 < -EPS);
}

// Process one pair given smem-gathered quantized coords; exact fallback if needed.
__device__ __forceinline__ void process_slot(
    const float2* __restrict__ pos,
    const unsigned char* __restrict__ s_coarse,
    float* hist,
    unsigned q1, unsigned q2, unsigned q3, unsigned q4,
    int i1, int i2, int i3, int i4)
{
    bool sent = (max(max(q1, q2), max(q3, q4)) == 0xFFFFu);

    int X1 = q1 & 0xFF, Y1 = q1 >> 8;
    int X2 = q2 & 0xFF, Y2 = q2 >> 8;
    int X3 = q3 & 0xFF, Y3 = q3 >> 8;
    int X4 = q4 & 0xFF, Y4 = q4 >> 8;

    // Exact integer orientation values on the quantized grid.
    int Rx = X4 - X3, Ry = Y4 - Y3;
    int Ax = X1 - X3, Ay = Y1 - Y3;
    int Bx = X2 - X3, By = Y2 - Y3;
    int d1 = Rx * Ay - Ry * Ax;
    int d2 = Rx * By - Ry * Bx;
    int Ux = X2 - X1, Uy = Y2 - Y1;
    int Cx = X3 - X1, Cy = Y3 - Y1;
    int Ex = X4 - X1, Ey = Y4 - Y1;
    int d3 = Ux * Cy - Uy * Cx;
    int d4 = Ux * Ey - Uy * Ex;

    // Error bounds via byte-SIMD: b = sum(|diffs|) + 2. |C*|==|A*| reused.
    unsigned vR = __vabsdiffu4(q4, q3);
    unsigned vA = __vabsdiffu4(q1, q3);
    unsigned vB = __vabsdiffu4(q2, q3);
    unsigned vU = __vabsdiffu4(q2, q1);
    unsigned vE = __vabsdiffu4(q4, q1);
    unsigned sR2 = __dp4a(vR, ONES4, 2u);
    unsigned sU2 = __dp4a(vU, ONES4, 2u);
    int b1 = (int)__dp4a(vA, ONES4, sR2);
    int b2 = (int)__dp4a(vB, ONES4, sR2);
    int b3 = (int)__dp4a(vA, ONES4, sU2);
    int b4 = (int)__dp4a(vE, ONES4, sU2);

    int l1 = abs(d1) - b1;
    int l2 = abs(d2) - b2;
    int l3 = abs(d3) - b3;
    int l4 = abs(d4) - b4;

    bool okA = (l1 > 0) & (l2 > 0) & (min(l1, 32767) * min(l2, 32767) > CERT_MIN);
    bool okB = (l3 > 0) & (l4 > 0) & (min(l3, 32767) * min(l4, 32767) > CERT_MIN);
    bool oppA = ((d1 ^ d2) < 0);
    bool oppB = ((d3 ^ d4) < 0);
    bool ct = okA & okB & oppA & oppB;
    bool cf = (okA & !oppA) | (okB & !oppB);

    bool cross = ct;
    if (sent | (!ct & !cf)) {
        // Uncertain: exact fp32 re-test via L1tex (rare lanes only).
        cross = xing_exact(__ldg(pos + i1), __ldg(pos + i2),
                           __ldg(pos + i3), __ldg(pos + i4));
    }
    if (cross) {
        unsigned char b = s_coarse[i1 >> 4];
        if (b == 255) b = g_batch8[i1];
        atomicAdd(&hist[b], 1.0f);
    }
}

__global__ void __launch_bounds__(CTA_THREADS, 1)
crossings_kernel(const float2* __restrict__ pos,
                 const int* __restrict__ epi,  // [2][2][P]: s1 | s2 | e1 | e2
                 float* __restrict__ out,
                 int P, int F, int NG16) {
    extern __shared__ char smem_raw[];
    unsigned short* s_q = (unsigned short*)smem_raw;                  // F_CAP*2
    unsigned char* s_coarse = (unsigned char*)(smem_raw + F_CAP * 2); // NG_CAP
    float* hist = (float*)(smem_raw + F_CAP * 2 + NG_CAP);

    // Preload quantized table + coarse batch table (coalesced int4 copies).
    {
        int n16 = (F * 2 + 15) >> 4;
        const uint4* src = (const uint4*)g_qpos16;
        uint4* dst = (uint4*)s_q;
        for (int i = threadIdx.x; i < n16; i += CTA_THREADS) dst[i] = src[i];
        int c16 = (NG16 + 15) >> 4;
        const uint4* csrc = (const uint4*)g_coarse16;
        uint4* cdst = (uint4*)s_coarse;
        for (int i = threadIdx.x; i < c16; i += CTA_THREADS) cdst[i] = csrc[i];
    }
    if (threadIdx.x < NUM_GRAPHS) hist[threadIdx.x] = 0.0f;
    __syncthreads();

    const int P2 = P >> 1;
    const int2* __restrict__ s1v = (const int2*)(epi);
    const int2* __restrict__ s2v = (const int2*)(epi + (size_t)P);
    const int2* __restrict__ e1v = (const int2*)(epi + 2 * (size_t)P);
    const int2* __restrict__ e2v = (const int2*)(epi + 3 * (size_t)P);

    const int lane = threadIdx.x & 31;

    // Warp-autonomous ticket loop with software-pipelined index prefetch.
    while (true) {
        int base;
        if (lane == 0) base = atomicAdd(&g_ticket, WCHUNK);
        base = __shfl_sync(0xFFFFFFFFu, base, 0);
        if (base >= P2) break;
        int lim = min(base + WCHUNK, P2);

        int v = base + lane;
        if (v >= lim) continue;

        // Prime: load current iteration's indices.
        int2 c_s1 = __ldg(s1v + v);
        int2 c_s2 = __ldg(s2v + v);
        int2 c_e1 = __ldg(e1v + v);
        int2 c_e2 = __ldg(e2v + v);

        while (true) {
            int vn = v + 32;
            bool more = vn < lim;
            int vp = more ? vn : v;   // clamped redundant load on last iter

            // Prefetch next iteration's indices (overlaps with compute below).
            int2 n_s1 = __ldg(s1v + vp);
            int2 n_s2 = __ldg(s2v + vp);
            int2 n_e1 = __ldg(e1v + vp);
            int2 n_e2 = __ldg(e2v + vp);

            // Gather quantized coords for both pairs (smem crossbar).
            unsigned qa1 = s_q[c_s1.x], qa2 = s_q[c_e1.x];
            unsigned qa3 = s_q[c_s2.x], qa4 = s_q[c_e2.x];
            unsigned qb1 = s_q[c_s1.y], qb2 = s_q[c_e1.y];
            unsigned qb3 = s_q[c_s2.y], qb4 = s_q[c_e2.y];

            process_slot(pos, s_coarse, hist, qa1, qa2, qa3, qa4,
                         c_s1.x, c_e1.x, c_s2.x, c_e2.x);
            process_slot(pos, s_coarse, hist, qb1, qb2, qb3, qb4,
                         c_s1.y, c_e1.y, c_s2.y, c_e2.y);

            if (!more) break;
            v = vn;
            c_s1 = n_s1; c_s2 = n_s2; c_e1 = n_e1; c_e2 = n_e2;
        }
    }

    // Scalar tail (P odd) — exact path, block 0 only.
    if (blockIdx.x == 0) {
        for (int p = ((P >> 1) << 1) + threadIdx.x; p < P; p += blockDim.x) {
            int t1 = __ldg(epi + p);
            int t2 = __ldg(epi + (size_t)P + p);
            int t3 = __ldg(epi + 2 * (size_t)P + p);
            int t4 = __ldg(epi + 3 * (size_t)P + p);
            if (xing_exact(__ldg(pos + t1), __ldg(pos + t3),
                           __ldg(pos + t2), __ldg(pos + t4)))
                atomicAdd(&hist[g_batch8[t1]], 1.0f);
        }
    }

    __syncthreads();
    for (int i = threadIdx.x; i < NUM_GRAPHS; i += CTA_THREADS) {
        float h = hist[i];
        if (h != 0.0f) atomicAdd(&out[i], h);
    }
}

extern "C" void kernel_launch(void* const* d_in, const int* in_sizes, int n_in,
                              void* d_out, int out_size) {
    // metadata order: node_pos f32[N,2], edge_index i32[2,E] (UNUSED),
    //                 apsp f32[E] (UNUSED), batch_index i32[N],
    //                 edge_pair_index i32[2,2,P]
    const float2* pos = (const float2*)d_in[0];
    const int* batch_index = (const int*)d_in[3];
    const int* epi = (const int*)d_in[4];
    float* out = (float*)d_out;

    int N = in_sizes[0] / 2;
    if (N > F_CAP) N = F_CAP;          // scratch bound (N is 100000 by spec)
    int P = in_sizes[4] / 4;
    int F = N;
    int NG16 = (N + 15) >> 4;
    if (NG16 > NG_CAP) NG16 = NG_CAP;

    int prep_threads = 256;
    int prep_blocks = (N + prep_threads - 1) / prep_threads;
    prep_kernel<<<prep_blocks, prep_threads>>>(batch_index, pos, out, N, F, NG16);

    size_t smem_bytes = (size_t)F_CAP * 2 + NG_CAP + NUM_GRAPHS * sizeof(float);
    cudaFuncSetAttribute(crossings_kernel,
                         cudaFuncAttributeMaxDynamicSharedMemorySize,
                         (int)smem_bytes);

    crossings_kernel<<<148, CTA_THREADS, smem_bytes>>>(pos, epi, out, P, F, NG16);
}